// round 8
// baseline (speedup 1.0000x reference)
#include <cuda_runtime.h>
#include <math.h>

#define BB 2048
#define KK 8
#define OO 256
#define II 512

#define G  8              // o's per block (one warp each)
#define OT (OO / G)       // 32 o-tiles
#define P  8              // b-slices per (k, o-tile)

// Scratch (no allocs allowed)
__device__ int g_cnt[KK];
__device__ int g_list[KK][BB];

// ---------------------------------------------------------------------------
// 1) argmax of gumbel-perturbed logits (== hard gumbel-softmax forward
//    one-hot) + per-k compaction. 1024 threads (2 rows each) to shorten the
//    serial MUFU-log chains. Within-k order is race-nondeterministic but
//    output values are order-independent.
// ---------------------------------------------------------------------------
__global__ __launch_bounds__(1024)
void sel_kernel(const float* __restrict__ mw,
                const float* __restrict__ u) {
    __shared__ int scnt[KK];
    const int tid = threadIdx.x;
    if (tid < KK) scnt[tid] = 0;
    __syncthreads();

    int myk[BB / 1024], mypos[BB / 1024];
#pragma unroll
    for (int r = 0; r < BB / 1024; r++) {
        const int b = tid + 1024 * r;
        float best = -INFINITY;
        int   bi   = 0;
#pragma unroll
        for (int k = 0; k < KK; k++) {
            float uv = u[b * KK + k];
            float g  = -logf(-logf(uv + 1e-10f) + 1e-10f);
            float v  = mw[k] + g;
            if (v > best) { best = v; bi = k; }   // strict > == first max (jnp.argmax)
        }
        myk[r]   = bi;
        mypos[r] = atomicAdd(&scnt[bi], 1);
    }
    __syncthreads();

#pragma unroll
    for (int r = 0; r < BB / 1024; r++)
        g_list[myk[r]][mypos[r]] = tid + 1024 * r;
    if (tid < KK) g_cnt[tid] = scnt[tid];
}

// ---------------------------------------------------------------------------
// 2) out[b,o] = sum_i X[b,i] * fmaf(exp(ls[k,o,i]), eps[b,o,i], mean[k,o,i])
//    Block = (k, o-tile, b-slice); whole block shares one k -> mean/std rows
//    in registers. THREE b's per iteration: 12 eps LDG.128 (__ldcs, evict-
//    first) batched up front for deep MLP; X loads inlined in the FMA chain
//    (L1 hits, shared by all 8 warps). ~110 regs -> occupancy 2.
// ---------------------------------------------------------------------------
__global__ __launch_bounds__(256, 2)
void main_kernel(const float* __restrict__ X,
                 const float* __restrict__ mean,
                 const float* __restrict__ ls,
                 const float* __restrict__ eps,
                 float*       __restrict__ out) {
    const int blk   = blockIdx.x;
    const int slice = blk % P;
    const int ot    = (blk / P) % OT;
    const int k     = blk / (P * OT);

    const int warp = threadIdx.x >> 5;
    const int lane = threadIdx.x & 31;
    const int o    = ot * G + warp;

    // (k,o) rows of mean and exp(log_sigma) -> registers, loaded once.
    const size_t rbase = ((size_t)k * OO + o) * II;
    const float4* mrow = reinterpret_cast<const float4*>(mean + rbase);
    const float4* lrow = reinterpret_cast<const float4*>(ls   + rbase);
    float4 mv[4], sv[4];
#pragma unroll
    for (int j = 0; j < 4; j++) {
        mv[j] = mrow[lane + 32 * j];
        float4 l4 = lrow[lane + 32 * j];
        sv[j].x = expf(l4.x); sv[j].y = expf(l4.y);
        sv[j].z = expf(l4.z); sv[j].w = expf(l4.w);
    }

    const int cnt   = g_cnt[k];
    const int start = (int)((long long)cnt * slice / P);
    const int end   = (int)((long long)cnt * (slice + 1) / P);
    int idx = start;

    // Remainder singles so the main loop is exact triples.
    const int rem = (end - start) % 3;
    for (int r = 0; r < rem; r++) {
        const int b = g_list[k][idx++];
        const float4* ev = reinterpret_cast<const float4*>(eps + ((size_t)b * OO + o) * II);
        const float4* Xv = reinterpret_cast<const float4*>(X   + (size_t)b * II);
        float4 e4[4];
#pragma unroll
        for (int j = 0; j < 4; j++) e4[j] = __ldcs(&ev[lane + 32 * j]);
        float acc = 0.f;
#pragma unroll
        for (int j = 0; j < 4; j++) {
            const float4 x4 = Xv[lane + 32 * j];
            acc = fmaf(x4.x, fmaf(sv[j].x, e4[j].x, mv[j].x), acc);
            acc = fmaf(x4.y, fmaf(sv[j].y, e4[j].y, mv[j].y), acc);
            acc = fmaf(x4.z, fmaf(sv[j].z, e4[j].z, mv[j].z), acc);
            acc = fmaf(x4.w, fmaf(sv[j].w, e4[j].w, mv[j].w), acc);
        }
#pragma unroll
        for (int off = 16; off; off >>= 1)
            acc += __shfl_xor_sync(0xffffffffu, acc, off);
        if (lane == 0) out[(size_t)b * OO + o] = acc;
    }

    // Main triples: 12 eps LDG.128 in flight per warp.
    for (; idx < end; idx += 3) {
        const int b0 = g_list[k][idx];
        const int b1 = g_list[k][idx + 1];
        const int b2 = g_list[k][idx + 2];
        const float4* e0 = reinterpret_cast<const float4*>(eps + ((size_t)b0 * OO + o) * II);
        const float4* e1 = reinterpret_cast<const float4*>(eps + ((size_t)b1 * OO + o) * II);
        const float4* e2 = reinterpret_cast<const float4*>(eps + ((size_t)b2 * OO + o) * II);
        const float4* x0 = reinterpret_cast<const float4*>(X   + (size_t)b0 * II);
        const float4* x1 = reinterpret_cast<const float4*>(X   + (size_t)b1 * II);
        const float4* x2 = reinterpret_cast<const float4*>(X   + (size_t)b2 * II);

        float4 ea[4], eb[4], ec[4];
#pragma unroll
        for (int j = 0; j < 4; j++) ea[j] = __ldcs(&e0[lane + 32 * j]);
#pragma unroll
        for (int j = 0; j < 4; j++) eb[j] = __ldcs(&e1[lane + 32 * j]);
#pragma unroll
        for (int j = 0; j < 4; j++) ec[j] = __ldcs(&e2[lane + 32 * j]);

        float acc0 = 0.f, acc1 = 0.f, acc2 = 0.f;
#pragma unroll
        for (int j = 0; j < 4; j++) {
            const float4 xa = x0[lane + 32 * j];   // L1 hit
            const float4 xb = x1[lane + 32 * j];
            const float4 xc = x2[lane + 32 * j];
            acc0 = fmaf(xa.x, fmaf(sv[j].x, ea[j].x, mv[j].x), acc0);
            acc1 = fmaf(xb.x, fmaf(sv[j].x, eb[j].x, mv[j].x), acc1);
            acc2 = fmaf(xc.x, fmaf(sv[j].x, ec[j].x, mv[j].x), acc2);
            acc0 = fmaf(xa.y, fmaf(sv[j].y, ea[j].y, mv[j].y), acc0);
            acc1 = fmaf(xb.y, fmaf(sv[j].y, eb[j].y, mv[j].y), acc1);
            acc2 = fmaf(xc.y, fmaf(sv[j].y, ec[j].y, mv[j].y), acc2);
            acc0 = fmaf(xa.z, fmaf(sv[j].z, ea[j].z, mv[j].z), acc0);
            acc1 = fmaf(xb.z, fmaf(sv[j].z, eb[j].z, mv[j].z), acc1);
            acc2 = fmaf(xc.z, fmaf(sv[j].z, ec[j].z, mv[j].z), acc2);
            acc0 = fmaf(xa.w, fmaf(sv[j].w, ea[j].w, mv[j].w), acc0);
            acc1 = fmaf(xb.w, fmaf(sv[j].w, eb[j].w, mv[j].w), acc1);
            acc2 = fmaf(xc.w, fmaf(sv[j].w, ec[j].w, mv[j].w), acc2);
        }
#pragma unroll
        for (int off = 16; off; off >>= 1) {
            acc0 += __shfl_xor_sync(0xffffffffu, acc0, off);
            acc1 += __shfl_xor_sync(0xffffffffu, acc1, off);
            acc2 += __shfl_xor_sync(0xffffffffu, acc2, off);
        }
        if (lane == 0) {
            out[(size_t)b0 * OO + o] = acc0;
            out[(size_t)b1 * OO + o] = acc1;
            out[(size_t)b2 * OO + o] = acc2;
        }
    }
}

// ---------------------------------------------------------------------------
// Inputs (metadata order): X[B,I], mix_weights[K], mean[K,O,I],
//                          log_sigma[K,O,I], u_gumbel[B,K], eps[B,O,I]
// Output: float32 [B,O]
// ---------------------------------------------------------------------------
extern "C" void kernel_launch(void* const* d_in, const int* in_sizes, int n_in,
                              void* d_out, int out_size) {
    const float* X    = (const float*)d_in[0];
    const float* mw   = (const float*)d_in[1];
    const float* mean = (const float*)d_in[2];
    const float* ls   = (const float*)d_in[3];
    const float* u    = (const float*)d_in[4];
    const float* eps  = (const float*)d_in[5];
    float* out        = (float*)d_out;

    sel_kernel<<<1, 1024>>>(mw, u);
    main_kernel<<<KK * OT * P, 256>>>(X, mean, ls, eps, out);
}